// round 10
// baseline (speedup 1.0000x reference)
#include <cuda_runtime.h>
#include <cstdint>

// YOLO layer: x (64, 255, 44, 44) f32 -> out (64, 5808, 85) f32.
//   out[b, a*1936 + s, c] = f(x[b, a*85 + c, s])
//   c==0:(sig+gx)*8  c==1:(sig+gy)*8  c==2:exp*aw  c==3:exp*ah  c>=4:sig
//
// R10: transpose thread mapping to lane==sl.
//  - LDG.32: per (warp, ch) lanes read 32 consecutive floats (128B coalesced)
//  - STS.32: lane-stride = 85 words, 85%32=21 coprime -> CONFLICT-FREE
//    (old mapping had stride 340 words -> 4-way conflict on every STS,
//     4x crossbar cycles in the same l1tex pipe that returns LDGs; l1tex=51%)
//  - warp w owns sl-group (w&3) [gx/gy computed once] and channel quads
//    (w>>2)+4k; quad 0 = the 4 special channels (warp-uniform branch);
//    ch 84 handled as single-channel task by cbase==1 warps.
// Write: ONE cp.async.bulk (shared->global) per tile, contiguous 43,520 B.
// Sigmoid: 4-instruction approx (FMUL, MUFU.EX2, FADD, MUFU.RCP).

#define G44   44
#define GG    1936
#define CH    85
#define NA    3
#define TS    128
#define NTHR  512

__constant__ float c_aw[NA] = {10.0f, 16.0f, 33.0f};   // scaled_anchor*STRIDE
__constant__ float c_ah[NA] = {13.0f, 30.0f, 23.0f};

__device__ __forceinline__ float sig_(float v) {
    float e;
    asm("ex2.approx.ftz.f32 %0, %1;" : "=f"(e) : "f"(v * -1.442695041f));
    float r;
    asm("rcp.approx.ftz.f32 %0, %1;" : "=f"(r) : "f"(1.0f + e));
    return r;
}

__device__ __forceinline__ float exp_(float v) {
    float e;
    asm("ex2.approx.ftz.f32 %0, %1;" : "=f"(e) : "f"(v * 1.442695041f));
    return e;
}

__global__ __launch_bounds__(NTHR, 3)
void yolo_kernel(const float* __restrict__ x, float* __restrict__ out) {
    __shared__ __align__(16) float sm[TS * CH];   // 43,520 B, output layout

    const int ba    = blockIdx.y;                 // b*NA + a (0..191)
    const int a     = ba % NA;
    const int s0    = blockIdx.x * TS;
    const int warp  = threadIdx.x >> 5;
    const int lane  = threadIdx.x & 31;
    const int slg   = warp & 3;                   // sl-group of this warp
    const int cbase = warp >> 2;                  // 0..3: channel-quad base
    const int valid = min(TS, GG - s0);           // 128, or 16 on last tile

    const int sl = (slg << 5) + lane;             // 0..127, lane-stride 1
    if (sl < valid) {
        const int s  = s0 + sl;
        const int gy = s / G44;
        const int gx = s - gy * G44;

        const float* __restrict__ ib = x + (size_t)ba * (CH * GG) + s;
        float* __restrict__ row = sm + sl * CH;

        // channel quads: chg = cbase + 4k, k=0..5 (chg 0..21; 21 = ch84 single)
        #pragma unroll
        for (int k = 0; k < 6; k++) {
            const int chg = cbase + (k << 2);
            if (chg > 21) break;                  // cbase 2,3 at k=5
            if (chg == 21) {                      // single channel 84
                row[84] = sig_(ib[(size_t)84 * GG]);
            } else {
                const int ch0 = chg << 2;
                const float v0 = ib[(size_t)(ch0 + 0) * GG];
                const float v1 = ib[(size_t)(ch0 + 1) * GG];
                const float v2 = ib[(size_t)(ch0 + 2) * GG];
                const float v3 = ib[(size_t)(ch0 + 3) * GG];
                float t0, t1, t2, t3;
                if (chg == 0) {                   // special channels 0..3
                    t0 = (sig_(v0) + (float)gx) * 8.0f;
                    t1 = (sig_(v1) + (float)gy) * 8.0f;
                    t2 = exp_(v2) * c_aw[a];
                    t3 = exp_(v3) * c_ah[a];
                } else {
                    t0 = sig_(v0); t1 = sig_(v1);
                    t2 = sig_(v2); t3 = sig_(v3);
                }
                // stride-85 across lanes: 85%32=21 coprime -> conflict-free
                row[ch0 + 0] = t0;
                row[ch0 + 1] = t1;
                row[ch0 + 2] = t2;
                row[ch0 + 3] = t3;
            }
        }
    }

    __syncthreads();

    // ---- write: single bulk async copy smem -> gmem (contiguous tile) ----
    if (threadIdx.x == 0) {
        uint32_t saddr;
        asm volatile("{ .reg .u64 t; cvta.to.shared.u64 t, %1; cvt.u32.u64 %0, t; }"
                     : "=r"(saddr) : "l"(sm));
        float* gptr = out + ((size_t)ba * GG + s0) * CH;   // 16B-aligned
        const uint32_t bytes = (uint32_t)(valid * CH * 4); // multiple of 16

        asm volatile("fence.proxy.async.shared::cta;" ::: "memory");
        asm volatile("cp.async.bulk.global.shared::cta.bulk_group [%0], [%1], %2;"
                     :: "l"(gptr), "r"(saddr), "r"(bytes) : "memory");
        asm volatile("cp.async.bulk.commit_group;" ::: "memory");
        asm volatile("cp.async.bulk.wait_group.read 0;" ::: "memory");
    }
}

extern "C" void kernel_launch(void* const* d_in, const int* in_sizes, int n_in,
                              void* d_out, int out_size) {
    const float* x = (const float*)d_in[0];
    float* out = (float*)d_out;

    dim3 grid((GG + TS - 1) / TS,   // 16 spatial tiles
              64 * NA);             // 192 (b,a) matrices
    yolo_kernel<<<grid, NTHR>>>(x, out);
}